// round 14
// baseline (speedup 1.0000x reference)
#include <cuda_runtime.h>
#include <cuda_fp16.h>

// BilateralSlice: grid (4,12,8,16,16) f32, guide (4,1,1024,1024) f32,
// out (4,12,1024,1024) f32.
//
// PERSISTENT kernel: 4 CTAs/SM, each loops over (b, 2-row) chunks with
// stride gridDim.x (kills the 0.54-wave quantization tail of the 2048-CTA
// launch). Double-buffered S: stage chunk k+1 (fused shuffle staging, R13)
// while computing/storing chunk k. 32-reg / 4 CTAs/SM target; block-split
// pixels (x = t, t+512); fp16 z-pair slice; __stcs STG.32 stores.

#define NB 4
#define NC 12
#define DG 8
#define HG 16
#define WG 16
#define HH 1024
#define WW 1024

constexpr int XSTRIDE = 100;             // S words per x (96 + 4 pad)
constexpr int RSTRIDE = WG * XSTRIDE;    // 1600 S words per row slice
constexpr int ROWS    = 2;
constexpr int THREADS = 512;
constexpr int RAWY4   = (NC * DG * WG) / 4;   // 384 float4 per lerped row
constexpr int NCHUNKS = NB * HH / ROWS;       // 2048

__device__ __forceinline__ void stage_one(
    int i, const float4* __restrict__ gb4,
    int y0a, int y1a, float fya, float wya,
    int y0b, int y1b, float fyb, float wyb,
    unsigned int* __restrict__ Sb)
{
    const int r  = i >= RAWY4;
    const int k  = i - r * RAWY4;        // c*32 + z*4 + x4
    const int c  = k >> 5;
    const int z  = (k >> 2) & 7;
    const int x4 = k & 3;

    const int   y0 = r ? y0b : y0a;
    const int   y1 = r ? y1b : y1a;
    const float fy = r ? fyb : fya;
    const float wy = r ? wyb : wya;

    const int base = (c * DG + z) * (HG * WG / 4) + x4;
    float4 v0 = gb4[base + y0 * (WG / 4)];
    float4 v1 = gb4[base + y1 * (WG / 4)];
    float4 v;
    v.x = wy * v0.x + fy * v1.x;
    v.y = wy * v0.y + fy * v1.y;
    v.z = wy * v0.z + fy * v1.z;
    v.w = wy * v0.w + fy * v1.w;

    // z+1 lerped values live in lane+4 (same c, same x4)
    float4 vn;
    vn.x = __shfl_down_sync(0xffffffffu, v.x, 4);
    vn.y = __shfl_down_sync(0xffffffffu, v.y, 4);
    vn.z = __shfl_down_sync(0xffffffffu, v.z, 4);
    vn.w = __shfl_down_sync(0xffffffffu, v.w, 4);
    if (z == DG - 1) vn = v;             // clamp z+1

    const float av[4] = {v.x,  v.y,  v.z,  v.w};
    const float bv[4] = {vn.x, vn.y, vn.z, vn.w};
    const int   sbase = r * RSTRIDE + z * 12 + c;
    #pragma unroll
    for (int j = 0; j < 4; ++j) {
        __half2 h = __floats2half2_rn(av[j], bv[j]);   // {v(z), v(z+1)}
        Sb[sbase + (x4 * 4 + j) * XSTRIDE] =
            *reinterpret_cast<unsigned int*>(&h);
    }
}

__device__ __forceinline__ void stage_chunk(
    int chunk, int tid,
    const float* __restrict__ grid,
    const float* __restrict__ guide,
    unsigned int* __restrict__ Sb,
    float* gv)                            // gv[4]: guide for (r,s)
{
    const int b     = chunk >> 9;
    const int ybase = (chunk & 511) * ROWS;

    // guide prefetch for this chunk
    const float* gpix = guide + (size_t)b * (HH * WW) + (size_t)ybase * WW;
    gv[0] = __ldg(&gpix[tid]);
    gv[1] = __ldg(&gpix[tid + THREADS]);
    gv[2] = __ldg(&gpix[WW + tid]);
    gv[3] = __ldg(&gpix[WW + tid + THREADS]);

    // y params for both rows
    const float iyfa = (float)(ybase)     * (15.0f / 1023.0f);
    const float iyfb = (float)(ybase + 1) * (15.0f / 1023.0f);
    const float y0fa = floorf(iyfa);
    const float y0fb = floorf(iyfb);
    const int   y0a  = (int)y0fa;
    const int   y0b  = (int)y0fb;
    const int   y1a  = min(y0a + 1, HG - 1);
    const int   y1b  = min(y0b + 1, HG - 1);
    const float fya  = iyfa - y0fa;
    const float fyb  = iyfb - y0fb;

    const float4* gb4 = reinterpret_cast<const float4*>(
        grid + (size_t)b * (NC * DG * HG * WG));
    stage_one(tid, gb4, y0a, y1a, fya, 1.0f - fya,
              y0b, y1b, fyb, 1.0f - fyb, Sb);
    if (tid < ROWS * RAWY4 - THREADS)
        stage_one(tid + THREADS, gb4, y0a, y1a, fya, 1.0f - fya,
                  y0b, y1b, fyb, 1.0f - fyb, Sb);
}

__global__ void __launch_bounds__(THREADS, 4)
bilateral_slice_kernel(const float* __restrict__ grid,
                       const float* __restrict__ guide,
                       float* __restrict__ out)
{
    __shared__ unsigned int S[2][ROWS * RSTRIDE];   // 2 x 12.8 KB

    const int tid = threadIdx.x;

    int chunk = blockIdx.x;
    float gv[4];
    stage_chunk(chunk, tid, grid, guide, S[0], gv);
    int buf = 0;

    for (; chunk < NCHUNKS; chunk += gridDim.x) {
        const int next = chunk + gridDim.x;
        __syncthreads();

        float gvn[4];
        if (next < NCHUNKS)
            stage_chunk(next, tid, grid, guide, S[buf ^ 1], gvn);

        // ---- compute + store current chunk from S[buf] ----
        const int b     = chunk >> 9;
        const int ybase = (chunk & 511) * ROWS;
        float* obase = out + (size_t)b * NC * (size_t)(HH * WW)
                           + (size_t)ybase * WW;
        const unsigned int* Sb = S[buf];

        #pragma unroll
        for (int r = 0; r < ROWS; ++r) {
            #pragma unroll
            for (int s = 0; s < 2; ++s) {
                const int   x    = tid + s * THREADS;
                const float ixf  = (float)x * (15.0f / 1023.0f);
                const float x0f  = floorf(ixf);
                const int   x0   = (int)x0f;
                const float fx   = ixf - x0f;
                const int   xa   = x0 * XSTRIDE;
                const int   xbv  = min(x0 + 1, WG - 1) * XSTRIDE;
                const __half2 hwx0 = __float2half2_rn(1.0f - fx);
                const __half2 hwx1 = __float2half2_rn(fx);

                float iz  = __saturatef(gv[r * 2 + s]) * (float)(DG - 1);
                float z0f = floorf(iz);
                int   z0  = (int)z0f;
                float fz  = iz - z0f;
                const float wz0 = 1.0f - fz;
                const float wz1 = fz;

                const int zo = r * RSTRIDE + z0 * 12;
                const uint4* pa = reinterpret_cast<const uint4*>(&Sb[xa + zo]);
                const uint4* pb = reinterpret_cast<const uint4*>(&Sb[xbv + zo]);
                uint4 A0 = pa[0], A1 = pa[1], A2 = pa[2];
                uint4 B0 = pb[0], B1 = pb[1], B2 = pb[2];

                const unsigned int Aw[12] = {A0.x, A0.y, A0.z, A0.w,
                                             A1.x, A1.y, A1.z, A1.w,
                                             A2.x, A2.y, A2.z, A2.w};
                const unsigned int Bw[12] = {B0.x, B0.y, B0.z, B0.w,
                                             B1.x, B1.y, B1.z, B1.w,
                                             B2.x, B2.y, B2.z, B2.w};

                float* opix = obase + (size_t)r * WW + x;
                #pragma unroll
                for (int c = 0; c < NC; ++c) {
                    __half2 a  = *reinterpret_cast<const __half2*>(&Aw[c]);
                    __half2 bb = *reinterpret_cast<const __half2*>(&Bw[c]);
                    __half2 t  = __hfma2(bb, hwx1, __hmul2(a, hwx0));
                    float2  f  = __half22float2(t);
                    __stcs(opix + (size_t)c * (HH * WW),
                           fmaf(wz0, f.x, wz1 * f.y));
                }
            }
        }

        gv[0] = gvn[0]; gv[1] = gvn[1]; gv[2] = gvn[2]; gv[3] = gvn[3];
        buf ^= 1;
    }
}

extern "C" void kernel_launch(void* const* d_in, const int* in_sizes, int n_in,
                              void* d_out, int out_size)
{
    const float* grid  = nullptr;
    const float* guide = nullptr;
    for (int i = 0; i < n_in; ++i) {
        if (in_sizes[i] == NB * NC * DG * HG * WG) grid  = (const float*)d_in[i];
        else if (in_sizes[i] == NB * HH * WW)      guide = (const float*)d_in[i];
    }

    int dev = 0, smCount = 148;
    cudaGetDevice(&dev);
    cudaDeviceGetAttribute(&smCount, cudaDevAttrMultiProcessorCount, dev);
    int nblocks = smCount * 4;
    if (nblocks > NCHUNKS) nblocks = NCHUNKS;

    bilateral_slice_kernel<<<nblocks, THREADS>>>(grid, guide, (float*)d_out);
}

// round 16
// speedup vs baseline: 1.2309x; 1.2309x over previous
#include <cuda_runtime.h>
#include <cuda_fp16.h>

// BilateralSlice: grid (4,12,8,16,16) f32, guide (4,1,1024,1024) f32,
// out (4,12,1024,1024) f32.
//
// R13 structure (fused shuffle staging -> fp16 z-pair slice; block-split
// pixels x = t, t+512; __stcs STG.32; 32-reg / 4 CTAs/SM) with ROWS=4:
// half the barrier/staging phases per pixel. Staging = 3 full 512-thread
// passes (no predication waste); y-params recomputed per pass to keep
// register liveness minimal.
// (Resubmission of round-15 kernel: previous bench died to container
// infrastructure, not kernel behavior.)

#define NB 4
#define NC 12
#define DG 8
#define HG 16
#define WG 16
#define HH 1024
#define WW 1024

constexpr int XSTRIDE = 100;             // S words per x (96 + 4 pad)
constexpr int RSTRIDE = WG * XSTRIDE;    // 1600 S words per row slice
constexpr int ROWS    = 4;
constexpr int THREADS = 512;
constexpr int RAWY4   = (NC * DG * WG) / 4;   // 384 float4 per lerped row

__device__ __forceinline__ void stage_one(
    int i, int ybase, const float4* __restrict__ gb4,
    unsigned int* __restrict__ S)
{
    const int r  = i / RAWY4;
    const int k  = i - r * RAWY4;        // c*32 + z*4 + x4
    const int c  = k >> 5;
    const int z  = (k >> 2) & 7;
    const int x4 = k & 3;

    // y params recomputed (cheap ALU, minimal liveness)
    const float iyf = (float)(ybase + r) * (15.0f / 1023.0f);
    const float y0f = floorf(iyf);
    const int   y0  = (int)y0f;
    const int   y1  = min(y0 + 1, HG - 1);
    const float fy  = iyf - y0f;
    const float wy  = 1.0f - fy;

    const int base = (c * DG + z) * (HG * WG / 4) + x4;
    float4 v0 = gb4[base + y0 * (WG / 4)];
    float4 v1 = gb4[base + y1 * (WG / 4)];
    float4 v;
    v.x = wy * v0.x + fy * v1.x;
    v.y = wy * v0.y + fy * v1.y;
    v.z = wy * v0.z + fy * v1.z;
    v.w = wy * v0.w + fy * v1.w;

    // z+1 lerped values live in lane+4 (same c, same x4)
    float4 vn;
    vn.x = __shfl_down_sync(0xffffffffu, v.x, 4);
    vn.y = __shfl_down_sync(0xffffffffu, v.y, 4);
    vn.z = __shfl_down_sync(0xffffffffu, v.z, 4);
    vn.w = __shfl_down_sync(0xffffffffu, v.w, 4);
    if (z == DG - 1) vn = v;             // clamp z+1

    const float av[4] = {v.x,  v.y,  v.z,  v.w};
    const float bv[4] = {vn.x, vn.y, vn.z, vn.w};
    const int   sbase = r * RSTRIDE + z * 12 + c;
    #pragma unroll
    for (int j = 0; j < 4; ++j) {
        __half2 h = __floats2half2_rn(av[j], bv[j]);   // {v(z), v(z+1)}
        S[sbase + (x4 * 4 + j) * XSTRIDE] =
            *reinterpret_cast<unsigned int*>(&h);
    }
}

__global__ void __launch_bounds__(THREADS, 4)
bilateral_slice_kernel(const float* __restrict__ grid,
                       const float* __restrict__ guide,
                       float* __restrict__ out)
{
    __shared__ unsigned int S[ROWS * RSTRIDE];    // 6400 words = 25.6 KB

    const int b     = blockIdx.x >> 8;
    const int rg    = blockIdx.x & 255;
    const int ybase = rg * ROWS;
    const int tid   = threadIdx.x;

    // ---- prefetch guide for all rows/slots (overlaps staging latency) ----
    const float* gpix = guide + (size_t)b * (HH * WW) + (size_t)ybase * WW;
    float gvp[ROWS][2];
    #pragma unroll
    for (int r = 0; r < ROWS; ++r) {
        gvp[r][0] = __ldg(&gpix[(size_t)r * WW + tid]);
        gvp[r][1] = __ldg(&gpix[(size_t)r * WW + tid + THREADS]);
    }

    // ---- fused staging: 3 full 512-thread passes (1536 trips) ----
    const float4* gb4 = reinterpret_cast<const float4*>(
        grid + (size_t)b * (NC * DG * HG * WG));
    #pragma unroll
    for (int p = 0; p < (ROWS * RAWY4) / THREADS; ++p)
        stage_one(tid + p * THREADS, ybase, gb4, S);
    __syncthreads();

    float* obase = out + (size_t)b * NC * (size_t)(HH * WW)
                       + (size_t)ybase * WW;

    #pragma unroll
    for (int r = 0; r < ROWS; ++r) {
        #pragma unroll
        for (int s = 0; s < 2; ++s) {
            const int   x    = tid + s * THREADS;
            const float ixf  = (float)x * (15.0f / 1023.0f);
            const float x0f  = floorf(ixf);
            const int   x0   = (int)x0f;
            const float fx   = ixf - x0f;
            const int   xa   = x0 * XSTRIDE;
            const int   xbv  = min(x0 + 1, WG - 1) * XSTRIDE;
            const __half2 hwx0 = __float2half2_rn(1.0f - fx);
            const __half2 hwx1 = __float2half2_rn(fx);

            const float gv = gvp[r][s];
            float iz  = __saturatef(gv) * (float)(DG - 1);
            float z0f = floorf(iz);
            int   z0  = (int)z0f;
            float fz  = iz - z0f;
            const float wz0 = 1.0f - fz;
            const float wz1 = fz;

            const int zo = r * RSTRIDE + z0 * 12;
            const uint4* pa = reinterpret_cast<const uint4*>(&S[xa + zo]);
            const uint4* pb = reinterpret_cast<const uint4*>(&S[xbv + zo]);
            uint4 A0 = pa[0], A1 = pa[1], A2 = pa[2];
            uint4 B0 = pb[0], B1 = pb[1], B2 = pb[2];

            const unsigned int Aw[12] = {A0.x, A0.y, A0.z, A0.w,
                                         A1.x, A1.y, A1.z, A1.w,
                                         A2.x, A2.y, A2.z, A2.w};
            const unsigned int Bw[12] = {B0.x, B0.y, B0.z, B0.w,
                                         B1.x, B1.y, B1.z, B1.w,
                                         B2.x, B2.y, B2.z, B2.w};

            float* opix = obase + (size_t)r * WW + x;
            #pragma unroll
            for (int c = 0; c < NC; ++c) {
                __half2 a  = *reinterpret_cast<const __half2*>(&Aw[c]);
                __half2 bb = *reinterpret_cast<const __half2*>(&Bw[c]);
                __half2 t  = __hfma2(bb, hwx1, __hmul2(a, hwx0));
                float2  f  = __half22float2(t);
                __stcs(opix + (size_t)c * (HH * WW),
                       fmaf(wz0, f.x, wz1 * f.y));
            }
        }
    }
}

extern "C" void kernel_launch(void* const* d_in, const int* in_sizes, int n_in,
                              void* d_out, int out_size)
{
    const float* grid  = nullptr;
    const float* guide = nullptr;
    for (int i = 0; i < n_in; ++i) {
        if (in_sizes[i] == NB * NC * DG * HG * WG) grid  = (const float*)d_in[i];
        else if (in_sizes[i] == NB * HH * WW)      guide = (const float*)d_in[i];
    }

    dim3 gridDim(NB * HH / ROWS);   // 1024 CTAs: one per (batch, 4-row group)
    bilateral_slice_kernel<<<gridDim, THREADS>>>(grid, guide, (float*)d_out);
}